// round 15
// baseline (speedup 1.0000x reference)
#include <cuda_runtime.h>
#include <math.h>
#include <stdint.h>

#define B_     8
#define SEQ_   1024
#define PRED_  1024
#define T_     2048
#define CIN_   21
#define MARK_  4
#define D_     512
#define H_     8
#define DH_    64
#define DFF_   2048
#define L_     3
#define NHASH_ 4
#define NB_    64
#define BH_    64
#define NTOK_  16384
#define NCHUNK_ 256
#define SORTN_ (BH_*NHASH_*T_)

typedef unsigned long long ull;

// ---------------- scratch (static device globals; no allocations) ----------------
__device__ float g_h[NTOK_*D_];
__device__ float g_ctx[NTOK_*D_];
__device__ float g_tmp[NTOK_*D_];
__device__ float g_ff[NTOK_*DFF_];     // holds fused QKV output (stride 1024), then FF1 out
__device__ float g_so[BH_*NHASH_*T_*DH_];
__device__ float g_slog[SORTN_];
__device__ int   g_buckets[SORTN_];
__device__ int   g_st[SORTN_];
__device__ int   g_undo[SORTN_];
__device__ float g_pe[T_*D_];

// ---------------- packed fp32x2 helpers (Blackwell; per-lane IEEE fp32 rn) -------
__device__ __forceinline__ ull pk2(float lo, float hi) {
    ull r; asm("mov.b64 %0, {%1, %2};" : "=l"(r) : "f"(lo), "f"(hi)); return r;
}
__device__ __forceinline__ void upk2(ull v, float &lo, float &hi) {
    asm("mov.b64 {%0, %1}, %2;" : "=f"(lo), "=f"(hi) : "l"(v));
}
__device__ __forceinline__ void fma2(ull &acc, ull a, ull b) {
    asm("fma.rn.f32x2 %0, %1, %2, %0;" : "+l"(acc) : "l"(a), "l"(b));
}

// ---------------- positional embedding table (double, matches numpy fp64 path) --------
__global__ void pe_kernel(float* __restrict__ pe)
{
    int idx = blockIdx.x * blockDim.x + threadIdx.x;
    if (idx >= T_*D_) return;
    int d = idx & 511;
    int t = idx >> 9;
    double expo = -(double)(d & ~1) * (9.210340371976184 / 512.0);
    double ang  = (double)t * exp(expo);
    pe[idx] = (float)((d & 1) ? cos(ang) : sin(ang));
}

// ---------------- embedding: circular conv1d(k=3) + PE + temporal ----------------
__global__ void embed_kernel(const float* __restrict__ xe, const float* __restrict__ xme,
                             const float* __restrict__ xd, const float* __restrict__ xmd,
                             const float* __restrict__ cw, const float* __restrict__ tw,
                             const float* __restrict__ pe, float* __restrict__ h)
{
    int idx = blockIdx.x * blockDim.x + threadIdx.x;
    if (idx >= NTOK_*D_) return;
    int d = idx & 511;
    int t = (idx >> 9) & (T_-1);
    int b = idx >> 20;

    float s = 0.f;
#pragma unroll
    for (int k = 0; k < 3; ++k) {
        int tt = t + k - 1;
        if (tt < 0) tt += T_;
        if (tt >= T_) tt -= T_;
        const float* xp = (tt < SEQ_) ? (xe + ((size_t)b*SEQ_ + tt)*CIN_)
                                      : (xd + ((size_t)b*PRED_ + (tt-SEQ_))*CIN_);
        const float* wp = cw + d*CIN_*3 + k;
#pragma unroll
        for (int c = 0; c < CIN_; ++c) s += xp[c] * wp[c*3];
    }
    s += pe[t*D_ + d];
    const float* xmp = (t < SEQ_) ? (xme + ((size_t)b*SEQ_ + t)*MARK_)
                                  : (xmd + ((size_t)b*PRED_ + (t-SEQ_))*MARK_);
#pragma unroll
    for (int c = 0; c < MARK_; ++c) s += xmp[c] * tw[d*MARK_ + c];
    h[idx] = s;
}

// ---------------- fp32 GEMM: C = A @ W^T (+bias)(+gelu) -------------------------
// BIT-IDENTICAL numerics to R1/R11/R14: each output element is one fp32 FMA chain
// over k = 0..K-1 ascending, single accumulator (f32x2 lanes = independent adjacent
// output columns). 128x128 block tile, 128 threads, 16x8 per-thread micro-tile:
// 32KB smem + ~26K regs per CTA -> 2 CTAs/SM, independent barriers hide latency.
#define BM_ 128
#define BN_ 128
#define BKT_ 16

__global__ void __launch_bounds__(128)
gemm_f32_kernel(const float* __restrict__ A, const float* __restrict__ W,
                const float* __restrict__ bias, float* __restrict__ C,
                int N, int K, int act)
{
    __shared__ float As[2][BKT_][BM_];
    __shared__ float Bs[2][BKT_][BN_];
    const int bm = blockIdx.y * BM_;
    const int bn = blockIdx.x * BN_;
    const int tid = threadIdx.x;
    const int tx = tid & 15, ty = tid >> 4;     // 8 row-groups x 16 col-groups

    ull acc2[16][4];
#pragma unroll
    for (int i = 0; i < 16; ++i)
#pragma unroll
        for (int j = 0; j < 4; ++j) acc2[i][j] = 0ull;

    float4 pa[4], pb[4];

#define GLOAD(k0)                                                           \
    do {                                                                    \
        const float* ap = &A[(size_t)(bm + tid) * K + (k0)];                \
        pa[0] = *(const float4*)(ap);      pa[1] = *(const float4*)(ap + 4);\
        pa[2] = *(const float4*)(ap + 8);  pa[3] = *(const float4*)(ap + 12);\
        const float* wp = &W[(size_t)(bn + tid) * K + (k0)];                \
        pb[0] = *(const float4*)(wp);      pb[1] = *(const float4*)(wp + 4);\
        pb[2] = *(const float4*)(wp + 8);  pb[3] = *(const float4*)(wp + 12);\
    } while (0)

#define SSTORE(buf)                                                         \
    do {                                                                    \
        _Pragma("unroll")                                                   \
        for (int q_ = 0; q_ < 4; ++q_) {                                    \
            As[buf][q_*4+0][tid] = pa[q_].x; As[buf][q_*4+1][tid] = pa[q_].y;\
            As[buf][q_*4+2][tid] = pa[q_].z; As[buf][q_*4+3][tid] = pa[q_].w;\
            Bs[buf][q_*4+0][tid] = pb[q_].x; Bs[buf][q_*4+1][tid] = pb[q_].y;\
            Bs[buf][q_*4+2][tid] = pb[q_].z; Bs[buf][q_*4+3][tid] = pb[q_].w;\
        }                                                                   \
    } while (0)

    GLOAD(0);
    SSTORE(0);
    __syncthreads();

    const int nk = K / BKT_;
    for (int kt = 0; kt < nk; ++kt) {
        int cur = kt & 1;
        if (kt + 1 < nk) GLOAD((kt + 1) * BKT_);
#pragma unroll
        for (int k = 0; k < BKT_; ++k) {
            float a[16];
            *(float4*)(a)      = *(float4*)&As[cur][k][ty*16];
            *(float4*)(a + 4)  = *(float4*)&As[cur][k][ty*16 + 4];
            *(float4*)(a + 8)  = *(float4*)&As[cur][k][ty*16 + 8];
            *(float4*)(a + 12) = *(float4*)&As[cur][k][ty*16 + 12];
            float4 wa = *(float4*)&Bs[cur][k][tx*8];
            float4 wb = *(float4*)&Bs[cur][k][tx*8 + 4];
            ull w2[4];
            w2[0] = pk2(wa.x, wa.y); w2[1] = pk2(wa.z, wa.w);
            w2[2] = pk2(wb.x, wb.y); w2[3] = pk2(wb.z, wb.w);
#pragma unroll
            for (int i = 0; i < 16; ++i) {
                ull ai = pk2(a[i], a[i]);
#pragma unroll
                for (int j = 0; j < 4; ++j)
                    fma2(acc2[i][j], ai, w2[j]);
            }
        }
        if (kt + 1 < nk) {
            __syncthreads();
            SSTORE(cur ^ 1);
            __syncthreads();
        }
    }
#undef GLOAD
#undef SSTORE

    // epilogue (same per-element expressions as before)
#pragma unroll
    for (int i = 0; i < 16; ++i) {
        int m = bm + ty*16 + i;
        float out[8];
#pragma unroll
        for (int j = 0; j < 4; ++j)
            upk2(acc2[i][j], out[2*j], out[2*j+1]);
#pragma unroll
        for (int j = 0; j < 8; ++j) {
            int n = bn + tx*8 + j;
            float v = out[j];
            if (bias) v += bias[n];
            if (act) v = 0.5f * v * (1.f + erff(v * 0.7071067811865475f));
            out[j] = v;
        }
        *(float4*)&C[(size_t)m * N + bn + tx*8]     = *(float4*)(out);
        *(float4*)&C[(size_t)m * N + bn + tx*8 + 4] = *(float4*)(out + 4);
    }
}

// ---------------- LSH hashing: argmax over [R, -R], R = qk . rot ----------------
// qkv: fused (NTOK, 1024) buffer; qk at cols [0,512), v at [512,1024)
__global__ void hash_kernel(const float* __restrict__ qkv, const float* __restrict__ rot,
                            int* __restrict__ buckets)
{
    __shared__ float sm[4][64];
    int warp = threadIdx.x >> 5, lane = threadIdx.x & 31;
    int item = blockIdx.x * 4 + warp;
    if (item >= BH_*T_) return;
    int bh = item / T_, t = item % T_;
    int b = bh >> 3, h = bh & 7;
    const float* row = qkv + ((size_t)(b*T_ + t))*1024 + h*DH_;
    sm[warp][lane]      = row[lane];
    sm[warp][lane + 32] = row[lane + 32];
    __syncwarp();
#pragma unroll
    for (int r = 0; r < NHASH_; ++r) {
        float s = 0.f;
#pragma unroll
        for (int f = 0; f < 64; ++f) s += sm[warp][f] * rot[f*(NHASH_*32) + r*32 + lane];
        float val = s; int idx = lane;
        if (-s > s) { val = -s; idx = lane + 32; }
#pragma unroll
        for (int off = 16; off > 0; off >>= 1) {
            float ov = __shfl_down_sync(0xffffffffu, val, off);
            int   oi = __shfl_down_sync(0xffffffffu, idx, off);
            if (ov > val || (ov == val && oi < idx)) { val = ov; idx = oi; }
        }
        if (lane == 0) buckets[(bh*NHASH_ + r)*T_ + t] = idx;
    }
}

// ---------------- stable counting sort per (bh, hash round) ----------------
__global__ void sort_kernel(const int* __restrict__ buckets, int* __restrict__ st,
                            int* __restrict__ undo)
{
    __shared__ int sb[T_];
    __shared__ int cnt[NB_];
    __shared__ int off[NB_];
    int tid = threadIdx.x;              // 64 threads
    int blk = blockIdx.x;               // bh*NHASH + r
    const int* bp = buckets + (size_t)blk * T_;
    for (int t = tid; t < T_; t += 64) sb[t] = bp[t];
    cnt[tid] = 0;
    __syncthreads();
    for (int t = tid; t < T_; t += 64) atomicAdd(&cnt[sb[t]], 1);
    __syncthreads();
    if (tid == 0) { int s = 0; for (int i = 0; i < NB_; ++i) { off[i] = s; s += cnt[i]; } }
    __syncthreads();
    int r = blk & 3;
    int o = off[tid];
    for (int t = 0; t < T_; ++t) {
        if (sb[t] == tid) {
            st  [(size_t)blk*T_ + o] = t;
            undo[(size_t)blk*T_ + t] = r*T_ + o;
            ++o;
        }
    }
}

// ---------------- chunked attention (32 queries, 64 keys incl. look-back) ----------------
__global__ void attn_kernel(const float* __restrict__ qkv, const int* __restrict__ st,
                            float* __restrict__ so, float* __restrict__ slog)
{
    __shared__ float sk[64][65];
    __shared__ float sv[64][65];
    __shared__ float sdots[32][65];
    __shared__ int   posk[64];
    int bh = blockIdx.x >> 8;
    int c  = blockIdx.x & 255;
    int b = bh >> 3, h = bh & 7;
    int pc = (c + 255) & 255;
    int j = threadIdx.x;                // 64 threads

    int sidx = bh*8192 + ((j < 32) ? (c*32 + j) : (pc*32 + (j - 32)));
    int pos = st[sidx];
    posk[j] = pos;
    const float4* qrow = (const float4*)(qkv + ((size_t)(b*T_ + pos))*1024 + h*DH_);
    const float4* vrow = (const float4*)(qkv + ((size_t)(b*T_ + pos))*1024 + 512 + h*DH_);
    float qreg[64];
    float nrm = 0.f;
#pragma unroll
    for (int q4 = 0; q4 < 16; ++q4) {
        float4 qa = qrow[q4];
        float4 va = vrow[q4];
        int d0 = q4*4;
        qreg[d0] = qa.x; qreg[d0+1] = qa.y; qreg[d0+2] = qa.z; qreg[d0+3] = qa.w;
        sv[j][d0] = va.x; sv[j][d0+1] = va.y; sv[j][d0+2] = va.z; sv[j][d0+3] = va.w;
        nrm += qa.x*qa.x + qa.y*qa.y + qa.z*qa.z + qa.w*qa.w;
    }
    float inv = 1.f / fmaxf(sqrtf(nrm), 1e-12f);
#pragma unroll
    for (int d = 0; d < 64; ++d) sk[j][d] = qreg[d] * inv;
    __syncthreads();

    if (j < 32) {
        int i = j;
        int pq = posk[i];
        float mx = -1e30f;
        for (int jj = 0; jj < 64; ++jj) {
            float s = 0.f;
#pragma unroll
            for (int d = 0; d < 64; ++d) s += qreg[d] * sk[jj][d];
            s *= 0.125f;
            if (pq == posk[jj]) s = -5e4f;
            sdots[i][jj] = s;
            mx = fmaxf(mx, s);
        }
        float se = 0.f;
        for (int jj = 0; jj < 64; ++jj) {
            float e = expf(sdots[i][jj] - mx);
            sdots[i][jj] = e;
            se += e;
        }
        float out[64];
#pragma unroll
        for (int d = 0; d < 64; ++d) out[d] = 0.f;
        for (int jj = 0; jj < 64; ++jj) {
            float p = sdots[i][jj];
#pragma unroll
            for (int d = 0; d < 64; ++d) out[d] += p * sv[jj][d];
        }
        float invse = 1.f / se;
        size_t obase = ((size_t)(bh*8192 + c*32 + i)) * 64;
#pragma unroll
        for (int d = 0; d < 64; ++d) so[obase + d] = out[d] * invse;
        slog[bh*8192 + c*32 + i] = mx + logf(se);
    }
}

// ---------------- unsort + combine hash rounds ----------------
__global__ void combine_kernel(const float* __restrict__ so, const float* __restrict__ slog,
                               const int* __restrict__ undo, float* __restrict__ ctx)
{
    int idx = blockIdx.x * blockDim.x + threadIdx.x;
    if (idx >= BH_*T_*DH_) return;
    int d  = idx & 63;
    int t  = (idx >> 6) & (T_-1);
    int bh = idx >> 17;
    float l[4]; int u[4];
    float mx = -1e30f;
#pragma unroll
    for (int r = 0; r < 4; ++r) {
        u[r] = undo[((size_t)bh*4 + r)*T_ + t];
        l[r] = slog[(size_t)bh*8192 + u[r]];
        mx = fmaxf(mx, l[r]);
    }
    float se = 0.f, o = 0.f;
#pragma unroll
    for (int r = 0; r < 4; ++r) {
        float w = expf(l[r] - mx);
        se += w;
        o  += w * so[((size_t)bh*8192 + u[r])*64 + d];
    }
    o /= se;
    int b = bh >> 3, h = bh & 7;
    ctx[((size_t)(b*T_ + t))*D_ + h*64 + d] = o;
}

// ---------------- (optional residual add) + layernorm ----------------
__global__ void add_ln_kernel(const float* __restrict__ in, const float* __restrict__ add,
                              const float* __restrict__ g, const float* __restrict__ bb,
                              float* __restrict__ out)
{
    __shared__ float red[256];
    int row = blockIdx.x, tid = threadIdx.x;
    const float* p = in + (size_t)row * D_;
    float x0 = p[tid], x1 = p[tid + 256];
    if (add) { const float* a = add + (size_t)row * D_; x0 += a[tid]; x1 += a[tid + 256]; }
    red[tid] = x0 + x1;
    __syncthreads();
    for (int s = 128; s > 0; s >>= 1) { if (tid < s) red[tid] += red[tid + s]; __syncthreads(); }
    float mean = red[0] * (1.f / 512.f);
    __syncthreads();
    float d0 = x0 - mean, d1 = x1 - mean;
    red[tid] = d0*d0 + d1*d1;
    __syncthreads();
    for (int s = 128; s > 0; s >>= 1) { if (tid < s) red[tid] += red[tid + s]; __syncthreads(); }
    float rs = rsqrtf(red[0] * (1.f / 512.f) + 1e-5f);
    out[(size_t)row*D_ + tid]       = d0 * rs * g[tid]       + bb[tid];
    out[(size_t)row*D_ + tid + 256] = d1 * rs * g[tid + 256] + bb[tid + 256];
}

// ---------------- final projection over last PRED rows ----------------
__global__ void proj_kernel(const float* __restrict__ hln, const float* __restrict__ w,
                            const float* __restrict__ pb, float* __restrict__ out)
{
    int idx = blockIdx.x * blockDim.x + threadIdx.x;
    if (idx >= B_*PRED_*CIN_) return;
    int c = idx % CIN_;
    int p = (idx / CIN_) % PRED_;
    int b = idx / (CIN_ * PRED_);
    const float* hr = hln + ((size_t)(b*T_ + SEQ_ + p)) * D_;
    const float* wr = w + c*D_;
    float s = pb[c];
    for (int d = 0; d < D_; ++d) s += hr[d] * wr[d];
    out[idx] = s;
}

// ---------------- driver ----------------
extern "C" void kernel_launch(void* const* d_in, const int* in_sizes, int n_in,
                              void* d_out, int out_size)
{
    const float* x_enc      = (const float*)d_in[0];
    const float* xm_enc     = (const float*)d_in[1];
    const float* x_dec      = (const float*)d_in[2];
    const float* xm_dec     = (const float*)d_in[3];
    const float* conv_w     = (const float*)d_in[4];
    const float* temporal_w = (const float*)d_in[5];
    const float* Wqk        = (const float*)d_in[6];
    const float* Wv         = (const float*)d_in[7];
    const float* Wo_w       = (const float*)d_in[8];
    const float* Wo_b       = (const float*)d_in[9];
    const float* rot        = (const float*)d_in[10];
    const float* ln1_g      = (const float*)d_in[11];
    const float* ln1_b      = (const float*)d_in[12];
    const float* ff1_w      = (const float*)d_in[13];
    const float* ff1_b      = (const float*)d_in[14];
    const float* ff2_w      = (const float*)d_in[15];
    const float* ff2_b      = (const float*)d_in[16];
    const float* ln2_g      = (const float*)d_in[17];
    const float* ln2_b      = (const float*)d_in[18];
    const float* lnf_g      = (const float*)d_in[19];
    const float* lnf_b      = (const float*)d_in[20];
    const float* proj_w     = (const float*)d_in[21];
    const float* proj_b     = (const float*)d_in[22];

    float *p_h, *p_ctx, *p_tmp, *p_ff, *p_so, *p_slog, *p_pe;
    int *p_buckets, *p_st, *p_undo;
    cudaGetSymbolAddress((void**)&p_h,      g_h);
    cudaGetSymbolAddress((void**)&p_ctx,    g_ctx);
    cudaGetSymbolAddress((void**)&p_tmp,    g_tmp);
    cudaGetSymbolAddress((void**)&p_ff,     g_ff);
    cudaGetSymbolAddress((void**)&p_so,     g_so);
    cudaGetSymbolAddress((void**)&p_slog,   g_slog);
    cudaGetSymbolAddress((void**)&p_buckets,g_buckets);
    cudaGetSymbolAddress((void**)&p_st,     g_st);
    cudaGetSymbolAddress((void**)&p_undo,   g_undo);
    cudaGetSymbolAddress((void**)&p_pe,     g_pe);

    pe_kernel<<<(T_*D_ + 255)/256, 256>>>(p_pe);
    embed_kernel<<<(NTOK_*D_ + 255)/256, 256>>>(x_enc, xm_enc, x_dec, xm_dec,
                                                conv_w, temporal_w, p_pe, p_h);

    for (int l = 0; l < L_; ++l) {
        // ---- fused QK+V projection into stride-1024 buffer (two GEMMs) ----
        gemm_f32_kernel<<<dim3(D_/BN_, NTOK_/BM_), 128>>>(p_h, Wqk + (size_t)l*D_*D_,
                                                          nullptr, p_ff, 1024, D_, 0);
        gemm_f32_kernel<<<dim3(D_/BN_, NTOK_/BM_), 128>>>(p_h, Wv + (size_t)l*D_*D_,
                                                          nullptr, p_ff + 512, 1024, D_, 0);
        // ---- LSH attention ----
        hash_kernel<<<(BH_*T_)/4, 128>>>(p_ff, rot + (size_t)l*DH_*NHASH_*32, p_buckets);
        sort_kernel<<<BH_*NHASH_, 64>>>(p_buckets, p_st, p_undo);
        attn_kernel<<<BH_*NCHUNK_, 64>>>(p_ff, p_st, p_so, p_slog);
        combine_kernel<<<(BH_*T_*DH_ + 255)/256, 256>>>(p_so, p_slog, p_undo, p_ctx);
        // ---- output projection ----
        gemm_f32_kernel<<<dim3(D_/BN_, NTOK_/BM_), 128>>>(p_ctx, Wo_w + (size_t)l*D_*D_,
                                                          Wo_b + l*D_, p_tmp, D_, D_, 0);
        add_ln_kernel<<<NTOK_, 256>>>(p_h, p_tmp, ln1_g + l*D_, ln1_b + l*D_, p_h);
        // ---- FFN ----
        gemm_f32_kernel<<<dim3(DFF_/BN_, NTOK_/BM_), 128>>>(p_h, ff1_w + (size_t)l*DFF_*D_,
                                                            ff1_b + l*DFF_, p_ff, DFF_, D_, 1);
        gemm_f32_kernel<<<dim3(D_/BN_, NTOK_/BM_), 128>>>(p_ff, ff2_w + (size_t)l*D_*DFF_,
                                                          ff2_b + l*D_, p_tmp, D_, DFF_, 0);
        add_ln_kernel<<<NTOK_, 256>>>(p_h, p_tmp, ln2_g + l*D_, ln2_b + l*D_, p_h);
    }

    add_ln_kernel<<<NTOK_, 256>>>(p_h, nullptr, lnf_g, lnf_b, p_ctx);
    proj_kernel<<<(B_*PRED_*CIN_ + 255)/256, 256>>>(p_ctx, proj_w, proj_b, (float*)d_out);
}

// round 16
// speedup vs baseline: 1.0377x; 1.0377x over previous
#include <cuda_runtime.h>
#include <math.h>
#include <stdint.h>

#define B_     8
#define SEQ_   1024
#define PRED_  1024
#define T_     2048
#define CIN_   21
#define MARK_  4
#define D_     512
#define H_     8
#define DH_    64
#define DFF_   2048
#define L_     3
#define NHASH_ 4
#define NB_    64
#define BH_    64
#define NTOK_  16384
#define NCHUNK_ 256
#define SORTN_ (BH_*NHASH_*T_)

typedef unsigned long long ull;

// ---------------- scratch (static device globals; no allocations) ----------------
__device__ float g_h[NTOK_*D_];
__device__ float g_ctx[NTOK_*D_];
__device__ float g_tmp[NTOK_*D_];
__device__ float g_ff[NTOK_*DFF_];     // holds fused QKV output (stride 1024), then FF1 out
__device__ float g_so[BH_*NHASH_*T_*DH_];
__device__ float g_slog[SORTN_];
__device__ int   g_buckets[SORTN_];
__device__ int   g_st[SORTN_];
__device__ int   g_undo[SORTN_];
__device__ float g_pe[T_*D_];

// ---------------- packed fp32x2 helpers (Blackwell; per-lane IEEE fp32 rn) -------
__device__ __forceinline__ ull pk2(float lo, float hi) {
    ull r; asm("mov.b64 %0, {%1, %2};" : "=l"(r) : "f"(lo), "f"(hi)); return r;
}
__device__ __forceinline__ void upk2(ull v, float &lo, float &hi) {
    asm("mov.b64 {%0, %1}, %2;" : "=f"(lo), "=f"(hi) : "l"(v));
}
__device__ __forceinline__ void fma2(ull &acc, ull a, ull b) {
    asm("fma.rn.f32x2 %0, %1, %2, %0;" : "+l"(acc) : "l"(a), "l"(b));
}

// ---------------- positional embedding table (double, matches numpy fp64 path) --------
__global__ void pe_kernel(float* __restrict__ pe)
{
    int idx = blockIdx.x * blockDim.x + threadIdx.x;
    if (idx >= T_*D_) return;
    int d = idx & 511;
    int t = idx >> 9;
    double expo = -(double)(d & ~1) * (9.210340371976184 / 512.0);
    double ang  = (double)t * exp(expo);
    pe[idx] = (float)((d & 1) ? cos(ang) : sin(ang));
}

// ---------------- embedding: circular conv1d(k=3) + PE + temporal ----------------
__global__ void embed_kernel(const float* __restrict__ xe, const float* __restrict__ xme,
                             const float* __restrict__ xd, const float* __restrict__ xmd,
                             const float* __restrict__ cw, const float* __restrict__ tw,
                             const float* __restrict__ pe, float* __restrict__ h)
{
    int idx = blockIdx.x * blockDim.x + threadIdx.x;
    if (idx >= NTOK_*D_) return;
    int d = idx & 511;
    int t = (idx >> 9) & (T_-1);
    int b = idx >> 20;

    float s = 0.f;
#pragma unroll
    for (int k = 0; k < 3; ++k) {
        int tt = t + k - 1;
        if (tt < 0) tt += T_;
        if (tt >= T_) tt -= T_;
        const float* xp = (tt < SEQ_) ? (xe + ((size_t)b*SEQ_ + tt)*CIN_)
                                      : (xd + ((size_t)b*PRED_ + (tt-SEQ_))*CIN_);
        const float* wp = cw + d*CIN_*3 + k;
#pragma unroll
        for (int c = 0; c < CIN_; ++c) s += xp[c] * wp[c*3];
    }
    s += pe[t*D_ + d];
    const float* xmp = (t < SEQ_) ? (xme + ((size_t)b*SEQ_ + t)*MARK_)
                                  : (xmd + ((size_t)b*PRED_ + (t-SEQ_))*MARK_);
#pragma unroll
    for (int c = 0; c < MARK_; ++c) s += xmp[c] * tw[d*MARK_ + c];
    h[idx] = s;
}

// ---------------- fp32 GEMM: C = A @ W^T (+bias)(+gelu) -------------------------
// BIT-IDENTICAL numerics to R1/R11/R14: each output element is one fp32 FMA chain
// over k = 0..K-1 ascending, single accumulator. f32x2 lanes = two ADJACENT OUTPUT
// ROWS: the A operand pair (As[k][m], As[k][m+1]) is read directly with one LDS.64
// (no packing MOVs); only the W broadcast needs pk2. 256x128 tile, 16x8/thread.
#define BM_ 256
#define BN_ 128
#define BKT_ 16

__global__ void __launch_bounds__(256)
gemm_f32_kernel(const float* __restrict__ A, const float* __restrict__ W,
                const float* __restrict__ bias, float* __restrict__ C,
                int N, int K, int act)
{
    __shared__ float As[2][BKT_][BM_];
    __shared__ float Bs[2][BKT_][BN_];
    const int bm = blockIdx.y * BM_;
    const int bn = blockIdx.x * BN_;
    const int tid = threadIdx.x;
    const int tx = tid & 15, ty = tid >> 4;     // 16 rows x 8 cols per thread
    const int rW = tid >> 1;                    // W loader row 0..127
    const int kh = (tid & 1) * 8;               // W loader k-half {0,8}

    ull acc2[8][8];                             // [row-pair][col]
#pragma unroll
    for (int i = 0; i < 8; ++i)
#pragma unroll
        for (int j = 0; j < 8; ++j) acc2[i][j] = 0ull;

    float4 pa[4], pb[2];

#define GLOAD(k0)                                                           \
    do {                                                                    \
        const float* ap = &A[(size_t)(bm + tid) * K + (k0)];                \
        pa[0] = *(const float4*)(ap);      pa[1] = *(const float4*)(ap + 4);\
        pa[2] = *(const float4*)(ap + 8);  pa[3] = *(const float4*)(ap + 12);\
        const float* wp = &W[(size_t)(bn + rW) * K + (k0) + kh];            \
        pb[0] = *(const float4*)(wp);      pb[1] = *(const float4*)(wp + 4);\
    } while (0)

#define SSTORE(buf)                                                         \
    do {                                                                    \
        _Pragma("unroll")                                                   \
        for (int q_ = 0; q_ < 4; ++q_) {                                    \
            As[buf][q_*4+0][tid] = pa[q_].x; As[buf][q_*4+1][tid] = pa[q_].y;\
            As[buf][q_*4+2][tid] = pa[q_].z; As[buf][q_*4+3][tid] = pa[q_].w;\
        }                                                                   \
        Bs[buf][kh+0][rW] = pb[0].x; Bs[buf][kh+1][rW] = pb[0].y;           \
        Bs[buf][kh+2][rW] = pb[0].z; Bs[buf][kh+3][rW] = pb[0].w;           \
        Bs[buf][kh+4][rW] = pb[1].x; Bs[buf][kh+5][rW] = pb[1].y;           \
        Bs[buf][kh+6][rW] = pb[1].z; Bs[buf][kh+7][rW] = pb[1].w;           \
    } while (0)

    GLOAD(0);
    SSTORE(0);
    __syncthreads();

    const int nk = K / BKT_;
    for (int kt = 0; kt < nk; ++kt) {
        int cur = kt & 1;
        if (kt + 1 < nk) GLOAD((kt + 1) * BKT_);
#pragma unroll
        for (int k = 0; k < BKT_; ++k) {
            // A row-pairs: direct LDS.64 of adjacent rows (ty*16 is 8B-aligned)
            ull a2[8];
#pragma unroll
            for (int p = 0; p < 8; ++p)
                a2[p] = *(const ull*)&As[cur][k][ty*16 + 2*p];
            float4 wa = *(float4*)&Bs[cur][k][tx*8];
            float4 wb = *(float4*)&Bs[cur][k][tx*8 + 4];
            ull w2[8];
            w2[0] = pk2(wa.x, wa.x); w2[1] = pk2(wa.y, wa.y);
            w2[2] = pk2(wa.z, wa.z); w2[3] = pk2(wa.w, wa.w);
            w2[4] = pk2(wb.x, wb.x); w2[5] = pk2(wb.y, wb.y);
            w2[6] = pk2(wb.z, wb.z); w2[7] = pk2(wb.w, wb.w);
#pragma unroll
            for (int p = 0; p < 8; ++p)
#pragma unroll
                for (int j = 0; j < 8; ++j)
                    fma2(acc2[p][j], a2[p], w2[j]);
        }
        if (kt + 1 < nk) {
            SSTORE(cur ^ 1);
            __syncthreads();
        }
    }
#undef GLOAD
#undef SSTORE

    // epilogue: lane0 = row ty*16+2p, lane1 = row ty*16+2p+1, cols tx*8..tx*8+7
#pragma unroll
    for (int p = 0; p < 8; ++p) {
        int m0 = bm + ty*16 + 2*p;
        float lo[8], hi[8];
#pragma unroll
        for (int j = 0; j < 8; ++j)
            upk2(acc2[p][j], lo[j], hi[j]);
#pragma unroll
        for (int j = 0; j < 8; ++j) {
            int n = bn + tx*8 + j;
            float v0 = lo[j], v1 = hi[j];
            if (bias) { float bv = bias[n]; v0 += bv; v1 += bv; }
            if (act) {
                v0 = 0.5f * v0 * (1.f + erff(v0 * 0.7071067811865475f));
                v1 = 0.5f * v1 * (1.f + erff(v1 * 0.7071067811865475f));
            }
            lo[j] = v0; hi[j] = v1;
        }
        *(float4*)&C[(size_t)m0 * N + bn + tx*8]         = *(float4*)(lo);
        *(float4*)&C[(size_t)m0 * N + bn + tx*8 + 4]     = *(float4*)(lo + 4);
        *(float4*)&C[(size_t)(m0+1) * N + bn + tx*8]     = *(float4*)(hi);
        *(float4*)&C[(size_t)(m0+1) * N + bn + tx*8 + 4] = *(float4*)(hi + 4);
    }
}

// ---------------- LSH hashing: argmax over [R, -R], R = qk . rot ----------------
// qkv: fused (NTOK, 1024) buffer; qk at cols [0,512), v at [512,1024)
__global__ void hash_kernel(const float* __restrict__ qkv, const float* __restrict__ rot,
                            int* __restrict__ buckets)
{
    __shared__ float sm[4][64];
    int warp = threadIdx.x >> 5, lane = threadIdx.x & 31;
    int item = blockIdx.x * 4 + warp;
    if (item >= BH_*T_) return;
    int bh = item / T_, t = item % T_;
    int b = bh >> 3, h = bh & 7;
    const float* row = qkv + ((size_t)(b*T_ + t))*1024 + h*DH_;
    sm[warp][lane]      = row[lane];
    sm[warp][lane + 32] = row[lane + 32];
    __syncwarp();
#pragma unroll
    for (int r = 0; r < NHASH_; ++r) {
        float s = 0.f;
#pragma unroll
        for (int f = 0; f < 64; ++f) s += sm[warp][f] * rot[f*(NHASH_*32) + r*32 + lane];
        float val = s; int idx = lane;
        if (-s > s) { val = -s; idx = lane + 32; }
#pragma unroll
        for (int off = 16; off > 0; off >>= 1) {
            float ov = __shfl_down_sync(0xffffffffu, val, off);
            int   oi = __shfl_down_sync(0xffffffffu, idx, off);
            if (ov > val || (ov == val && oi < idx)) { val = ov; idx = oi; }
        }
        if (lane == 0) buckets[(bh*NHASH_ + r)*T_ + t] = idx;
    }
}

// ---------------- stable counting sort per (bh, hash round) ----------------
__global__ void sort_kernel(const int* __restrict__ buckets, int* __restrict__ st,
                            int* __restrict__ undo)
{
    __shared__ int sb[T_];
    __shared__ int cnt[NB_];
    __shared__ int off[NB_];
    int tid = threadIdx.x;              // 64 threads
    int blk = blockIdx.x;               // bh*NHASH + r
    const int* bp = buckets + (size_t)blk * T_;
    for (int t = tid; t < T_; t += 64) sb[t] = bp[t];
    cnt[tid] = 0;
    __syncthreads();
    for (int t = tid; t < T_; t += 64) atomicAdd(&cnt[sb[t]], 1);
    __syncthreads();
    if (tid == 0) { int s = 0; for (int i = 0; i < NB_; ++i) { off[i] = s; s += cnt[i]; } }
    __syncthreads();
    int r = blk & 3;
    int o = off[tid];
    for (int t = 0; t < T_; ++t) {
        if (sb[t] == tid) {
            st  [(size_t)blk*T_ + o] = t;
            undo[(size_t)blk*T_ + t] = r*T_ + o;
            ++o;
        }
    }
}

// ---------------- chunked attention (32 queries, 64 keys incl. look-back) ----------------
__global__ void attn_kernel(const float* __restrict__ qkv, const int* __restrict__ st,
                            float* __restrict__ so, float* __restrict__ slog)
{
    __shared__ float sk[64][65];
    __shared__ float sv[64][65];
    __shared__ float sdots[32][65];
    __shared__ int   posk[64];
    int bh = blockIdx.x >> 8;
    int c  = blockIdx.x & 255;
    int b = bh >> 3, h = bh & 7;
    int pc = (c + 255) & 255;
    int j = threadIdx.x;                // 64 threads

    int sidx = bh*8192 + ((j < 32) ? (c*32 + j) : (pc*32 + (j - 32)));
    int pos = st[sidx];
    posk[j] = pos;
    const float4* qrow = (const float4*)(qkv + ((size_t)(b*T_ + pos))*1024 + h*DH_);
    const float4* vrow = (const float4*)(qkv + ((size_t)(b*T_ + pos))*1024 + 512 + h*DH_);
    float qreg[64];
    float nrm = 0.f;
#pragma unroll
    for (int q4 = 0; q4 < 16; ++q4) {
        float4 qa = qrow[q4];
        float4 va = vrow[q4];
        int d0 = q4*4;
        qreg[d0] = qa.x; qreg[d0+1] = qa.y; qreg[d0+2] = qa.z; qreg[d0+3] = qa.w;
        sv[j][d0] = va.x; sv[j][d0+1] = va.y; sv[j][d0+2] = va.z; sv[j][d0+3] = va.w;
        nrm += qa.x*qa.x + qa.y*qa.y + qa.z*qa.z + qa.w*qa.w;
    }
    float inv = 1.f / fmaxf(sqrtf(nrm), 1e-12f);
#pragma unroll
    for (int d = 0; d < 64; ++d) sk[j][d] = qreg[d] * inv;
    __syncthreads();

    if (j < 32) {
        int i = j;
        int pq = posk[i];
        float mx = -1e30f;
        for (int jj = 0; jj < 64; ++jj) {
            float s = 0.f;
#pragma unroll
            for (int d = 0; d < 64; ++d) s += qreg[d] * sk[jj][d];
            s *= 0.125f;
            if (pq == posk[jj]) s = -5e4f;
            sdots[i][jj] = s;
            mx = fmaxf(mx, s);
        }
        float se = 0.f;
        for (int jj = 0; jj < 64; ++jj) {
            float e = expf(sdots[i][jj] - mx);
            sdots[i][jj] = e;
            se += e;
        }
        float out[64];
#pragma unroll
        for (int d = 0; d < 64; ++d) out[d] = 0.f;
        for (int jj = 0; jj < 64; ++jj) {
            float p = sdots[i][jj];
#pragma unroll
            for (int d = 0; d < 64; ++d) out[d] += p * sv[jj][d];
        }
        float invse = 1.f / se;
        size_t obase = ((size_t)(bh*8192 + c*32 + i)) * 64;
#pragma unroll
        for (int d = 0; d < 64; ++d) so[obase + d] = out[d] * invse;
        slog[bh*8192 + c*32 + i] = mx + logf(se);
    }
}

// ---------------- unsort + combine hash rounds ----------------
__global__ void combine_kernel(const float* __restrict__ so, const float* __restrict__ slog,
                               const int* __restrict__ undo, float* __restrict__ ctx)
{
    int idx = blockIdx.x * blockDim.x + threadIdx.x;
    if (idx >= BH_*T_*DH_) return;
    int d  = idx & 63;
    int t  = (idx >> 6) & (T_-1);
    int bh = idx >> 17;
    float l[4]; int u[4];
    float mx = -1e30f;
#pragma unroll
    for (int r = 0; r < 4; ++r) {
        u[r] = undo[((size_t)bh*4 + r)*T_ + t];
        l[r] = slog[(size_t)bh*8192 + u[r]];
        mx = fmaxf(mx, l[r]);
    }
    float se = 0.f, o = 0.f;
#pragma unroll
    for (int r = 0; r < 4; ++r) {
        float w = expf(l[r] - mx);
        se += w;
        o  += w * so[((size_t)bh*8192 + u[r])*64 + d];
    }
    o /= se;
    int b = bh >> 3, h = bh & 7;
    ctx[((size_t)(b*T_ + t))*D_ + h*64 + d] = o;
}

// ---------------- (optional residual add) + layernorm ----------------
__global__ void add_ln_kernel(const float* __restrict__ in, const float* __restrict__ add,
                              const float* __restrict__ g, const float* __restrict__ bb,
                              float* __restrict__ out)
{
    __shared__ float red[256];
    int row = blockIdx.x, tid = threadIdx.x;
    const float* p = in + (size_t)row * D_;
    float x0 = p[tid], x1 = p[tid + 256];
    if (add) { const float* a = add + (size_t)row * D_; x0 += a[tid]; x1 += a[tid + 256]; }
    red[tid] = x0 + x1;
    __syncthreads();
    for (int s = 128; s > 0; s >>= 1) { if (tid < s) red[tid] += red[tid + s]; __syncthreads(); }
    float mean = red[0] * (1.f / 512.f);
    __syncthreads();
    float d0 = x0 - mean, d1 = x1 - mean;
    red[tid] = d0*d0 + d1*d1;
    __syncthreads();
    for (int s = 128; s > 0; s >>= 1) { if (tid < s) red[tid] += red[tid + s]; __syncthreads(); }
    float rs = rsqrtf(red[0] * (1.f / 512.f) + 1e-5f);
    out[(size_t)row*D_ + tid]       = d0 * rs * g[tid]       + bb[tid];
    out[(size_t)row*D_ + tid + 256] = d1 * rs * g[tid + 256] + bb[tid + 256];
}

// ---------------- final projection over last PRED rows ----------------
__global__ void proj_kernel(const float* __restrict__ hln, const float* __restrict__ w,
                            const float* __restrict__ pb, float* __restrict__ out)
{
    int idx = blockIdx.x * blockDim.x + threadIdx.x;
    if (idx >= B_*PRED_*CIN_) return;
    int c = idx % CIN_;
    int p = (idx / CIN_) % PRED_;
    int b = idx / (CIN_ * PRED_);
    const float* hr = hln + ((size_t)(b*T_ + SEQ_ + p)) * D_;
    const float* wr = w + c*D_;
    float s = pb[c];
    for (int d = 0; d < D_; ++d) s += hr[d] * wr[d];
    out[idx] = s;
}

// ---------------- driver ----------------
extern "C" void kernel_launch(void* const* d_in, const int* in_sizes, int n_in,
                              void* d_out, int out_size)
{
    const float* x_enc      = (const float*)d_in[0];
    const float* xm_enc     = (const float*)d_in[1];
    const float* x_dec      = (const float*)d_in[2];
    const float* xm_dec     = (const float*)d_in[3];
    const float* conv_w     = (const float*)d_in[4];
    const float* temporal_w = (const float*)d_in[5];
    const float* Wqk        = (const float*)d_in[6];
    const float* Wv         = (const float*)d_in[7];
    const float* Wo_w       = (const float*)d_in[8];
    const float* Wo_b       = (const float*)d_in[9];
    const float* rot        = (const float*)d_in[10];
    const float* ln1_g      = (const float*)d_in[11];
    const float* ln1_b      = (const float*)d_in[12];
    const float* ff1_w      = (const float*)d_in[13];
    const float* ff1_b      = (const float*)d_in[14];
    const float* ff2_w      = (const float*)d_in[15];
    const float* ff2_b      = (const float*)d_in[16];
    const float* ln2_g      = (const float*)d_in[17];
    const float* ln2_b      = (const float*)d_in[18];
    const float* lnf_g      = (const float*)d_in[19];
    const float* lnf_b      = (const float*)d_in[20];
    const float* proj_w     = (const float*)d_in[21];
    const float* proj_b     = (const float*)d_in[22];

    float *p_h, *p_ctx, *p_tmp, *p_ff, *p_so, *p_slog, *p_pe;
    int *p_buckets, *p_st, *p_undo;
    cudaGetSymbolAddress((void**)&p_h,      g_h);
    cudaGetSymbolAddress((void**)&p_ctx,    g_ctx);
    cudaGetSymbolAddress((void**)&p_tmp,    g_tmp);
    cudaGetSymbolAddress((void**)&p_ff,     g_ff);
    cudaGetSymbolAddress((void**)&p_so,     g_so);
    cudaGetSymbolAddress((void**)&p_slog,   g_slog);
    cudaGetSymbolAddress((void**)&p_buckets,g_buckets);
    cudaGetSymbolAddress((void**)&p_st,     g_st);
    cudaGetSymbolAddress((void**)&p_undo,   g_undo);
    cudaGetSymbolAddress((void**)&p_pe,     g_pe);

    pe_kernel<<<(T_*D_ + 255)/256, 256>>>(p_pe);
    embed_kernel<<<(NTOK_*D_ + 255)/256, 256>>>(x_enc, xm_enc, x_dec, xm_dec,
                                                conv_w, temporal_w, p_pe, p_h);

    for (int l = 0; l < L_; ++l) {
        // ---- fused QK+V projection into stride-1024 buffer (two GEMMs) ----
        gemm_f32_kernel<<<dim3(D_/BN_, NTOK_/BM_), 256>>>(p_h, Wqk + (size_t)l*D_*D_,
                                                          nullptr, p_ff, 1024, D_, 0);
        gemm_f32_kernel<<<dim3(D_/BN_, NTOK_/BM_), 256>>>(p_h, Wv + (size_t)l*D_*D_,
                                                          nullptr, p_ff + 512, 1024, D_, 0);
        // ---- LSH attention ----
        hash_kernel<<<(BH_*T_)/4, 128>>>(p_ff, rot + (size_t)l*DH_*NHASH_*32, p_buckets);
        sort_kernel<<<BH_*NHASH_, 64>>>(p_buckets, p_st, p_undo);
        attn_kernel<<<BH_*NCHUNK_, 64>>>(p_ff, p_st, p_so, p_slog);
        combine_kernel<<<(BH_*T_*DH_ + 255)/256, 256>>>(p_so, p_slog, p_undo, p_ctx);
        // ---- output projection ----
        gemm_f32_kernel<<<dim3(D_/BN_, NTOK_/BM_), 256>>>(p_ctx, Wo_w + (size_t)l*D_*D_,
                                                          Wo_b + l*D_, p_tmp, D_, D_, 0);
        add_ln_kernel<<<NTOK_, 256>>>(p_h, p_tmp, ln1_g + l*D_, ln1_b + l*D_, p_h);
        // ---- FFN ----
        gemm_f32_kernel<<<dim3(DFF_/BN_, NTOK_/BM_), 256>>>(p_h, ff1_w + (size_t)l*DFF_*D_,
                                                            ff1_b + l*DFF_, p_ff, DFF_, D_, 1);
        gemm_f32_kernel<<<dim3(D_/BN_, NTOK_/BM_), 256>>>(p_ff, ff2_w + (size_t)l*D_*DFF_,
                                                          ff2_b + l*D_, p_tmp, D_, DFF_, 0);
        add_ln_kernel<<<NTOK_, 256>>>(p_h, p_tmp, ln2_g + l*D_, ln2_b + l*D_, p_h);
    }

    add_ln_kernel<<<NTOK_, 256>>>(p_h, nullptr, lnf_g, lnf_b, p_ctx);
    proj_kernel<<<(B_*PRED_*CIN_ + 255)/256, 256>>>(p_ctx, proj_w, proj_b, (float*)d_out);
}

// round 17
// speedup vs baseline: 1.1781x; 1.1353x over previous
#include <cuda_runtime.h>
#include <math.h>
#include <stdint.h>

#define B_     8
#define SEQ_   1024
#define PRED_  1024
#define T_     2048
#define CIN_   21
#define MARK_  4
#define D_     512
#define H_     8
#define DH_    64
#define DFF_   2048
#define L_     3
#define NHASH_ 4
#define NB_    64
#define BH_    64
#define NTOK_  16384
#define NCHUNK_ 256
#define SORTN_ (BH_*NHASH_*T_)

typedef unsigned long long ull;

// ---------------- scratch (static device globals; no allocations) ----------------
__device__ float g_h[NTOK_*D_];
__device__ float g_ctx[NTOK_*D_];
__device__ float g_tmp[NTOK_*D_];
__device__ float g_ff[NTOK_*DFF_];     // holds fused QKV output (stride 1024), then FF1 out
__device__ float g_so[BH_*NHASH_*T_*DH_];
__device__ float g_slog[SORTN_];
__device__ int   g_buckets[SORTN_];
__device__ int   g_st[SORTN_];
__device__ int   g_undo[SORTN_];
__device__ float g_pe[T_*D_];

// ---------------- packed fp32x2 helpers (Blackwell; per-lane IEEE fp32 rn) -------
__device__ __forceinline__ ull pk2(float lo, float hi) {
    ull r; asm("mov.b64 %0, {%1, %2};" : "=l"(r) : "f"(lo), "f"(hi)); return r;
}
__device__ __forceinline__ void upk2(ull v, float &lo, float &hi) {
    asm("mov.b64 {%0, %1}, %2;" : "=f"(lo), "=f"(hi) : "l"(v));
}
__device__ __forceinline__ void fma2(ull &acc, ull a, ull b) {
    asm("fma.rn.f32x2 %0, %1, %2, %0;" : "+l"(acc) : "l"(a), "l"(b));
}

// ---------------- positional embedding table (double, matches numpy fp64 path) --------
__global__ void pe_kernel(float* __restrict__ pe)
{
    int idx = blockIdx.x * blockDim.x + threadIdx.x;
    if (idx >= T_*D_) return;
    int d = idx & 511;
    int t = idx >> 9;
    double expo = -(double)(d & ~1) * (9.210340371976184 / 512.0);
    double ang  = (double)t * exp(expo);
    pe[idx] = (float)((d & 1) ? cos(ang) : sin(ang));
}

// ---------------- embedding: circular conv1d(k=3) + PE + temporal ----------------
__global__ void embed_kernel(const float* __restrict__ xe, const float* __restrict__ xme,
                             const float* __restrict__ xd, const float* __restrict__ xmd,
                             const float* __restrict__ cw, const float* __restrict__ tw,
                             const float* __restrict__ pe, float* __restrict__ h)
{
    int idx = blockIdx.x * blockDim.x + threadIdx.x;
    if (idx >= NTOK_*D_) return;
    int d = idx & 511;
    int t = (idx >> 9) & (T_-1);
    int b = idx >> 20;

    float s = 0.f;
#pragma unroll
    for (int k = 0; k < 3; ++k) {
        int tt = t + k - 1;
        if (tt < 0) tt += T_;
        if (tt >= T_) tt -= T_;
        const float* xp = (tt < SEQ_) ? (xe + ((size_t)b*SEQ_ + tt)*CIN_)
                                      : (xd + ((size_t)b*PRED_ + (tt-SEQ_))*CIN_);
        const float* wp = cw + d*CIN_*3 + k;
#pragma unroll
        for (int c = 0; c < CIN_; ++c) s += xp[c] * wp[c*3];
    }
    s += pe[t*D_ + d];
    const float* xmp = (t < SEQ_) ? (xme + ((size_t)b*SEQ_ + t)*MARK_)
                                  : (xmd + ((size_t)b*PRED_ + (t-SEQ_))*MARK_);
#pragma unroll
    for (int c = 0; c < MARK_; ++c) s += xmp[c] * tw[d*MARK_ + c];
    h[idx] = s;
}

// ---------------- fp32 GEMM: C = A @ W^T (+bias)(+gelu) -------------------------
// BIT-IDENTICAL numerics: each output element = one fp32 FMA chain over k ascending.
// f32x2 lanes = two adjacent output rows (A pair via single LDS.64). 256x128 tile.
#define BM_ 256
#define BN_ 128
#define BKT_ 16

__global__ void __launch_bounds__(256)
gemm_f32_kernel(const float* __restrict__ A, const float* __restrict__ W,
                const float* __restrict__ bias, float* __restrict__ C,
                int N, int K, int act)
{
    __shared__ float As[2][BKT_][BM_];
    __shared__ float Bs[2][BKT_][BN_];
    const int bm = blockIdx.y * BM_;
    const int bn = blockIdx.x * BN_;
    const int tid = threadIdx.x;
    const int tx = tid & 15, ty = tid >> 4;
    const int rW = tid >> 1;
    const int kh = (tid & 1) * 8;

    ull acc2[8][8];
#pragma unroll
    for (int i = 0; i < 8; ++i)
#pragma unroll
        for (int j = 0; j < 8; ++j) acc2[i][j] = 0ull;

    float4 pa[4], pb[2];

#define GLOAD(k0)                                                           \
    do {                                                                    \
        const float* ap = &A[(size_t)(bm + tid) * K + (k0)];                \
        pa[0] = *(const float4*)(ap);      pa[1] = *(const float4*)(ap + 4);\
        pa[2] = *(const float4*)(ap + 8);  pa[3] = *(const float4*)(ap + 12);\
        const float* wp = &W[(size_t)(bn + rW) * K + (k0) + kh];            \
        pb[0] = *(const float4*)(wp);      pb[1] = *(const float4*)(wp + 4);\
    } while (0)

#define SSTORE(buf)                                                         \
    do {                                                                    \
        _Pragma("unroll")                                                   \
        for (int q_ = 0; q_ < 4; ++q_) {                                    \
            As[buf][q_*4+0][tid] = pa[q_].x; As[buf][q_*4+1][tid] = pa[q_].y;\
            As[buf][q_*4+2][tid] = pa[q_].z; As[buf][q_*4+3][tid] = pa[q_].w;\
        }                                                                   \
        Bs[buf][kh+0][rW] = pb[0].x; Bs[buf][kh+1][rW] = pb[0].y;           \
        Bs[buf][kh+2][rW] = pb[0].z; Bs[buf][kh+3][rW] = pb[0].w;           \
        Bs[buf][kh+4][rW] = pb[1].x; Bs[buf][kh+5][rW] = pb[1].y;           \
        Bs[buf][kh+6][rW] = pb[1].z; Bs[buf][kh+7][rW] = pb[1].w;           \
    } while (0)

    GLOAD(0);
    SSTORE(0);
    __syncthreads();

    const int nk = K / BKT_;
    for (int kt = 0; kt < nk; ++kt) {
        int cur = kt & 1;
        if (kt + 1 < nk) GLOAD((kt + 1) * BKT_);
#pragma unroll
        for (int k = 0; k < BKT_; ++k) {
            ull a2[8];
#pragma unroll
            for (int p = 0; p < 8; ++p)
                a2[p] = *(const ull*)&As[cur][k][ty*16 + 2*p];
            float4 wa = *(float4*)&Bs[cur][k][tx*8];
            float4 wb = *(float4*)&Bs[cur][k][tx*8 + 4];
            ull w2[8];
            w2[0] = pk2(wa.x, wa.x); w2[1] = pk2(wa.y, wa.y);
            w2[2] = pk2(wa.z, wa.z); w2[3] = pk2(wa.w, wa.w);
            w2[4] = pk2(wb.x, wb.x); w2[5] = pk2(wb.y, wb.y);
            w2[6] = pk2(wb.z, wb.z); w2[7] = pk2(wb.w, wb.w);
#pragma unroll
            for (int p = 0; p < 8; ++p)
#pragma unroll
                for (int j = 0; j < 8; ++j)
                    fma2(acc2[p][j], a2[p], w2[j]);
        }
        if (kt + 1 < nk) {
            SSTORE(cur ^ 1);
            __syncthreads();
        }
    }
#undef GLOAD
#undef SSTORE

#pragma unroll
    for (int p = 0; p < 8; ++p) {
        int m0 = bm + ty*16 + 2*p;
        float lo[8], hi[8];
#pragma unroll
        for (int j = 0; j < 8; ++j)
            upk2(acc2[p][j], lo[j], hi[j]);
#pragma unroll
        for (int j = 0; j < 8; ++j) {
            int n = bn + tx*8 + j;
            float v0 = lo[j], v1 = hi[j];
            if (bias) { float bv = bias[n]; v0 += bv; v1 += bv; }
            if (act) {
                v0 = 0.5f * v0 * (1.f + erff(v0 * 0.7071067811865475f));
                v1 = 0.5f * v1 * (1.f + erff(v1 * 0.7071067811865475f));
            }
            lo[j] = v0; hi[j] = v1;
        }
        *(float4*)&C[(size_t)m0 * N + bn + tx*8]         = *(float4*)(lo);
        *(float4*)&C[(size_t)m0 * N + bn + tx*8 + 4]     = *(float4*)(lo + 4);
        *(float4*)&C[(size_t)(m0+1) * N + bn + tx*8]     = *(float4*)(hi);
        *(float4*)&C[(size_t)(m0+1) * N + bn + tx*8 + 4] = *(float4*)(hi + 4);
    }
}

// ---------------- LSH hashing: argmax over [R, -R], R = qk . rot ----------------
// rot cached in SMEM once per block (32KB); 8 warps x 8 items each = 64 items/block.
// Per-lane dot order, values, and shfl argmax reduction identical to the R1 kernel.
__global__ void __launch_bounds__(256)
hash_kernel(const float* __restrict__ qkv, const float* __restrict__ rot,
            int* __restrict__ buckets)
{
    __shared__ float srot[64*128];      // rot[f*128 + c]
    __shared__ float sq[8][64];
    int tid = threadIdx.x;
    int warp = tid >> 5, lane = tid & 31;

    // load rot (8192 floats) cooperatively
    for (int i = tid*4; i < 64*128; i += 256*4)
        *(float4*)&srot[i] = *(const float4*)&rot[i];
    __syncthreads();

    for (int it = 0; it < 8; ++it) {
        int item = blockIdx.x * 64 + warp * 8 + it;
        int bh = item / T_, t = item % T_;
        int b = bh >> 3, h = bh & 7;
        const float* row = qkv + ((size_t)(b*T_ + t))*1024 + h*DH_;
        sq[warp][lane]      = row[lane];
        sq[warp][lane + 32] = row[lane + 32];
        __syncwarp();
#pragma unroll
        for (int r = 0; r < NHASH_; ++r) {
            float s = 0.f;
#pragma unroll
            for (int f = 0; f < 64; ++f) s += sq[warp][f] * srot[f*128 + r*32 + lane];
            float val = s; int idx = lane;
            if (-s > s) { val = -s; idx = lane + 32; }
#pragma unroll
            for (int off = 16; off > 0; off >>= 1) {
                float ov = __shfl_down_sync(0xffffffffu, val, off);
                int   oi = __shfl_down_sync(0xffffffffu, idx, off);
                if (ov > val || (ov == val && oi < idx)) { val = ov; idx = oi; }
            }
            if (lane == 0) buckets[(bh*NHASH_ + r)*T_ + t] = idx;
        }
        __syncwarp();
    }
}

// ---------------- stable counting sort per (bh, hash round) ----------------
__global__ void sort_kernel(const int* __restrict__ buckets, int* __restrict__ st,
                            int* __restrict__ undo)
{
    __shared__ int sb[T_];
    __shared__ int cnt[NB_];
    __shared__ int off[NB_];
    int tid = threadIdx.x;              // 64 threads
    int blk = blockIdx.x;               // bh*NHASH + r
    const int* bp = buckets + (size_t)blk * T_;
    for (int t = tid; t < T_; t += 64) sb[t] = bp[t];
    cnt[tid] = 0;
    __syncthreads();
    for (int t = tid; t < T_; t += 64) atomicAdd(&cnt[sb[t]], 1);
    __syncthreads();
    if (tid == 0) { int s = 0; for (int i = 0; i < NB_; ++i) { off[i] = s; s += cnt[i]; } }
    __syncthreads();
    int r = blk & 3;
    int o = off[tid];
    for (int t = 0; t < T_; ++t) {
        if (sb[t] == tid) {
            st  [(size_t)blk*T_ + o] = t;
            undo[(size_t)blk*T_ + t] = r*T_ + o;
            ++o;
        }
    }
}

// ---------------- chunked attention (32 queries, 64 keys incl. look-back) ----------------
// All 64 threads active in every phase. Per-element fp math sequences identical to the
// original: dot chains over d ascending, softmax mx/se serial over jj, out[d] chains
// over jj ascending. Key term recomputed as RN(raw*inv) = bit-identical to stored sk.
__global__ void attn_kernel(const float* __restrict__ qkv, const int* __restrict__ st,
                            float* __restrict__ so, float* __restrict__ slog)
{
    __shared__ float sraw[64][65];     // raw q/k rows
    __shared__ float sv[64][65];
    __shared__ float sdots[32][65];
    __shared__ float sinvn[64];        // key normalization 1/max(|q|,1e-12)
    __shared__ float sinvse[32];       // 1/se per query
    __shared__ int   posk[64];
    int bh = blockIdx.x >> 8;
    int c  = blockIdx.x & 255;
    int b = bh >> 3, h = bh & 7;
    int pc = (c + 255) & 255;
    int j = threadIdx.x;                // 64 threads

    // ---- phase 1: load rows, compute norms ----
    int sidx = bh*8192 + ((j < 32) ? (c*32 + j) : (pc*32 + (j - 32)));
    int pos = st[sidx];
    posk[j] = pos;
    const float4* qrow = (const float4*)(qkv + ((size_t)(b*T_ + pos))*1024 + h*DH_);
    const float4* vrow = (const float4*)(qkv + ((size_t)(b*T_ + pos))*1024 + 512 + h*DH_);
    float nrm = 0.f;
#pragma unroll
    for (int q4 = 0; q4 < 16; ++q4) {
        float4 qa = qrow[q4];
        float4 va = vrow[q4];
        int d0 = q4*4;
        sraw[j][d0] = qa.x; sraw[j][d0+1] = qa.y; sraw[j][d0+2] = qa.z; sraw[j][d0+3] = qa.w;
        sv[j][d0] = va.x; sv[j][d0+1] = va.y; sv[j][d0+2] = va.z; sv[j][d0+3] = va.w;
        nrm += qa.x*qa.x + qa.y*qa.y + qa.z*qa.z + qa.w*qa.w;
    }
    sinvn[j] = 1.f / fmaxf(sqrtf(nrm), 1e-12f);
    __syncthreads();

    // ---- phase 2a: dots (64 threads: query j&31, key half j>>5) ----
    {
        int i = j & 31;
        int jj0 = (j & 32);
        int pq = posk[i];
        for (int jl = 0; jl < 32; ++jl) {
            int jj = jj0 + jl;
            float inv = sinvn[jj];
            float s = 0.f;
#pragma unroll
            for (int d = 0; d < 64; ++d) s += sraw[i][d] * (sraw[jj][d] * inv);
            s *= 0.125f;
            if (pq == posk[jj]) s = -5e4f;
            sdots[i][jj] = s;
        }
    }
    __syncthreads();

    // ---- phase 2c: softmax stats (serial over jj, threads < 32) ----
    if (j < 32) {
        int i = j;
        float mx = -1e30f;
        for (int jj = 0; jj < 64; ++jj) mx = fmaxf(mx, sdots[i][jj]);
        float se = 0.f;
        for (int jj = 0; jj < 64; ++jj) {
            float e = expf(sdots[i][jj] - mx);
            sdots[i][jj] = e;
            se += e;
        }
        sinvse[i] = 1.f / se;
        slog[bh*8192 + c*32 + i] = mx + logf(se);
    }
    __syncthreads();

    // ---- phase 2b: output (64 threads: query j&31, d-half j>>5) ----
    {
        int i = j & 31;
        int db = (j & 32);
        float out[32];
#pragma unroll
        for (int dl = 0; dl < 32; ++dl) out[dl] = 0.f;
        for (int jj = 0; jj < 64; ++jj) {
            float p = sdots[i][jj];
#pragma unroll
            for (int dl = 0; dl < 32; ++dl) out[dl] += p * sv[jj][db + dl];
        }
        float invse = sinvse[i];
        size_t obase = ((size_t)(bh*8192 + c*32 + i)) * 64 + db;
#pragma unroll
        for (int dl = 0; dl < 32; ++dl) so[obase + dl] = out[dl] * invse;
    }
}

// ---------------- unsort + combine hash rounds ----------------
__global__ void combine_kernel(const float* __restrict__ so, const float* __restrict__ slog,
                               const int* __restrict__ undo, float* __restrict__ ctx)
{
    int idx = blockIdx.x * blockDim.x + threadIdx.x;
    if (idx >= BH_*T_*DH_) return;
    int d  = idx & 63;
    int t  = (idx >> 6) & (T_-1);
    int bh = idx >> 17;
    float l[4]; int u[4];
    float mx = -1e30f;
#pragma unroll
    for (int r = 0; r < 4; ++r) {
        u[r] = undo[((size_t)bh*4 + r)*T_ + t];
        l[r] = slog[(size_t)bh*8192 + u[r]];
        mx = fmaxf(mx, l[r]);
    }
    float se = 0.f, o = 0.f;
#pragma unroll
    for (int r = 0; r < 4; ++r) {
        float w = expf(l[r] - mx);
        se += w;
        o  += w * so[((size_t)bh*8192 + u[r])*64 + d];
    }
    o /= se;
    int b = bh >> 3, h = bh & 7;
    ctx[((size_t)(b*T_ + t))*D_ + h*64 + d] = o;
}

// ---------------- (optional residual add) + layernorm ----------------
__global__ void add_ln_kernel(const float* __restrict__ in, const float* __restrict__ add,
                              const float* __restrict__ g, const float* __restrict__ bb,
                              float* __restrict__ out)
{
    __shared__ float red[256];
    int row = blockIdx.x, tid = threadIdx.x;
    const float* p = in + (size_t)row * D_;
    float x0 = p[tid], x1 = p[tid + 256];
    if (add) { const float* a = add + (size_t)row * D_; x0 += a[tid]; x1 += a[tid + 256]; }
    red[tid] = x0 + x1;
    __syncthreads();
    for (int s = 128; s > 0; s >>= 1) { if (tid < s) red[tid] += red[tid + s]; __syncthreads(); }
    float mean = red[0] * (1.f / 512.f);
    __syncthreads();
    float d0 = x0 - mean, d1 = x1 - mean;
    red[tid] = d0*d0 + d1*d1;
    __syncthreads();
    for (int s = 128; s > 0; s >>= 1) { if (tid < s) red[tid] += red[tid + s]; __syncthreads(); }
    float rs = rsqrtf(red[0] * (1.f / 512.f) + 1e-5f);
    out[(size_t)row*D_ + tid]       = d0 * rs * g[tid]       + bb[tid];
    out[(size_t)row*D_ + tid + 256] = d1 * rs * g[tid + 256] + bb[tid + 256];
}

// ---------------- final projection over last PRED rows ----------------
__global__ void proj_kernel(const float* __restrict__ hln, const float* __restrict__ w,
                            const float* __restrict__ pb, float* __restrict__ out)
{
    int idx = blockIdx.x * blockDim.x + threadIdx.x;
    if (idx >= B_*PRED_*CIN_) return;
    int c = idx % CIN_;
    int p = (idx / CIN_) % PRED_;
    int b = idx / (CIN_ * PRED_);
    const float* hr = hln + ((size_t)(b*T_ + SEQ_ + p)) * D_;
    const float* wr = w + c*D_;
    float s = pb[c];
    for (int d = 0; d < D_; ++d) s += hr[d] * wr[d];
    out[idx] = s;
}

// ---------------- driver ----------------
extern "C" void kernel_launch(void* const* d_in, const int* in_sizes, int n_in,
                              void* d_out, int out_size)
{
    const float* x_enc      = (const float*)d_in[0];
    const float* xm_enc     = (const float*)d_in[1];
    const float* x_dec      = (const float*)d_in[2];
    const float* xm_dec     = (const float*)d_in[3];
    const float* conv_w     = (const float*)d_in[4];
    const float* temporal_w = (const float*)d_in[5];
    const float* Wqk        = (const float*)d_in[6];
    const float* Wv         = (const float*)d_in[7];
    const float* Wo_w       = (const float*)d_in[8];
    const float* Wo_b       = (const float*)d_in[9];
    const float* rot        = (const float*)d_in[10];
    const float* ln1_g      = (const float*)d_in[11];
    const float* ln1_b      = (const float*)d_in[12];
    const float* ff1_w      = (const float*)d_in[13];
    const float* ff1_b      = (const float*)d_in[14];
    const float* ff2_w      = (const float*)d_in[15];
    const float* ff2_b      = (const float*)d_in[16];
    const float* ln2_g      = (const float*)d_in[17];
    const float* ln2_b      = (const float*)d_in[18];
    const float* lnf_g      = (const float*)d_in[19];
    const float* lnf_b      = (const float*)d_in[20];
    const float* proj_w     = (const float*)d_in[21];
    const float* proj_b     = (const float*)d_in[22];

    float *p_h, *p_ctx, *p_tmp, *p_ff, *p_so, *p_slog, *p_pe;
    int *p_buckets, *p_st, *p_undo;
    cudaGetSymbolAddress((void**)&p_h,      g_h);
    cudaGetSymbolAddress((void**)&p_ctx,    g_ctx);
    cudaGetSymbolAddress((void**)&p_tmp,    g_tmp);
    cudaGetSymbolAddress((void**)&p_ff,     g_ff);
    cudaGetSymbolAddress((void**)&p_so,     g_so);
    cudaGetSymbolAddress((void**)&p_slog,   g_slog);
    cudaGetSymbolAddress((void**)&p_buckets,g_buckets);
    cudaGetSymbolAddress((void**)&p_st,     g_st);
    cudaGetSymbolAddress((void**)&p_undo,   g_undo);
    cudaGetSymbolAddress((void**)&p_pe,     g_pe);

    pe_kernel<<<(T_*D_ + 255)/256, 256>>>(p_pe);
    embed_kernel<<<(NTOK_*D_ + 255)/256, 256>>>(x_enc, xm_enc, x_dec, xm_dec,
                                                conv_w, temporal_w, p_pe, p_h);

    for (int l = 0; l < L_; ++l) {
        // ---- fused QK+V projection into stride-1024 buffer (two GEMMs) ----
        gemm_f32_kernel<<<dim3(D_/BN_, NTOK_/BM_), 256>>>(p_h, Wqk + (size_t)l*D_*D_,
                                                          nullptr, p_ff, 1024, D_, 0);
        gemm_f32_kernel<<<dim3(D_/BN_, NTOK_/BM_), 256>>>(p_h, Wv + (size_t)l*D_*D_,
                                                          nullptr, p_ff + 512, 1024, D_, 0);
        // ---- LSH attention ----
        hash_kernel<<<(BH_*T_)/64, 256>>>(p_ff, rot + (size_t)l*DH_*NHASH_*32, p_buckets);
        sort_kernel<<<BH_*NHASH_, 64>>>(p_buckets, p_st, p_undo);
        attn_kernel<<<BH_*NCHUNK_, 64>>>(p_ff, p_st, p_so, p_slog);
        combine_kernel<<<(BH_*T_*DH_ + 255)/256, 256>>>(p_so, p_slog, p_undo, p_ctx);
        // ---- output projection ----
        gemm_f32_kernel<<<dim3(D_/BN_, NTOK_/BM_), 256>>>(p_ctx, Wo_w + (size_t)l*D_*D_,
                                                          Wo_b + l*D_, p_tmp, D_, D_, 0);
        add_ln_kernel<<<NTOK_, 256>>>(p_h, p_tmp, ln1_g + l*D_, ln1_b + l*D_, p_h);
        // ---- FFN ----
        gemm_f32_kernel<<<dim3(DFF_/BN_, NTOK_/BM_), 256>>>(p_h, ff1_w + (size_t)l*DFF_*D_,
                                                            ff1_b + l*DFF_, p_ff, DFF_, D_, 1);
        gemm_f32_kernel<<<dim3(D_/BN_, NTOK_/BM_), 256>>>(p_ff, ff2_w + (size_t)l*D_*DFF_,
                                                          ff2_b + l*D_, p_tmp, D_, DFF_, 0);
        add_ln_kernel<<<NTOK_, 256>>>(p_h, p_tmp, ln2_g + l*D_, ln2_b + l*D_, p_h);
    }

    add_ln_kernel<<<NTOK_, 256>>>(p_h, nullptr, lnf_g, lnf_b, p_ctx);
    proj_kernel<<<(B_*PRED_*CIN_ + 255)/256, 256>>>(p_ctx, proj_w, proj_b, (float*)d_out);
}